// round 2
// baseline (speedup 1.0000x reference)
#include <cuda_runtime.h>

// out[b] = sum_h sum_k x[b,k]*W[h,k] * (0.5*2.0)
//        = sum_k x[b,k] * S[k],  S[k] = sum_h W[h,k]
// Two HBM-bound passes (~128 MB total).

#define BATCH 4096
#define IN    4096
#define HID   4096

__device__ float g_S[IN];  // column sums of W (zeroed via graph memset node)

// Column-sum of W [HID, IN] row-major.
// grid.x covers k (float4 granularity), grid.y splits HID rows.
__global__ void colsum_kernel(const float* __restrict__ W) {
    const int rows_per_block = 32;
    int k4 = blockIdx.x * blockDim.x + threadIdx.x;   // float4 index along k
    int k  = k4 * 4;
    int h0 = blockIdx.y * rows_per_block;

    float4 acc = make_float4(0.f, 0.f, 0.f, 0.f);
    const float4* Wv = reinterpret_cast<const float4*>(W);
    const int stride4 = IN / 4;

    #pragma unroll 8
    for (int r = 0; r < rows_per_block; r++) {
        float4 v = Wv[(long)(h0 + r) * stride4 + k4];
        acc.x += v.x; acc.y += v.y; acc.z += v.z; acc.w += v.w;
    }
    atomicAdd(&g_S[k + 0], acc.x);
    atomicAdd(&g_S[k + 1], acc.y);
    atomicAdd(&g_S[k + 2], acc.z);
    atomicAdd(&g_S[k + 3], acc.w);
}

// Warp-per-row matvec: out[b] = dot(x[b,:], S). No smem, no __syncthreads.
__global__ void matvec_kernel(const float* __restrict__ x,
                              float* __restrict__ out) {
    int warp = (blockIdx.x * blockDim.x + threadIdx.x) >> 5;  // global warp = row
    int lane = threadIdx.x & 31;

    const float4* xv = reinterpret_cast<const float4*>(x + (long)warp * IN);
    const float4* Sv = reinterpret_cast<const float4*>(g_S);

    float a0 = 0.f, a1 = 0.f, a2 = 0.f, a3 = 0.f;
    #pragma unroll 8
    for (int i = lane; i < IN / 4; i += 32) {   // 32 iterations per lane
        float4 xx = xv[i];
        float4 ss = Sv[i];     // L2-resident (16 KB, shared by all warps)
        a0 = fmaf(xx.x, ss.x, a0);
        a1 = fmaf(xx.y, ss.y, a1);
        a2 = fmaf(xx.z, ss.z, a2);
        a3 = fmaf(xx.w, ss.w, a3);
    }
    float sum = (a0 + a1) + (a2 + a3);

    #pragma unroll
    for (int off = 16; off > 0; off >>= 1)
        sum += __shfl_xor_sync(0xFFFFFFFFu, sum, off);

    if (lane == 0) out[warp] = sum * (0.5f * 2.0f);
}

extern "C" void kernel_launch(void* const* d_in, const int* in_sizes, int n_in,
                              void* d_out, int out_size) {
    const float* x = (const float*)d_in[0];
    const float* W = (const float*)d_in[1];
    float* out = (float*)d_out;

    // Zero g_S with a memset node (much cheaper than a kernel node).
    void* s_ptr = nullptr;
    cudaGetSymbolAddress(&s_ptr, g_S);
    cudaMemsetAsync(s_ptr, 0, IN * sizeof(float));

    // colsum: blockDim 256, 4 k's per thread -> grid.x = 4; 32 rows/block -> grid.y = 128
    dim3 cs_grid(IN / (256 * 4), HID / 32);
    colsum_kernel<<<cs_grid, 256>>>(W);

    // matvec: 8 warps (rows) per 256-thread block -> 512 blocks
    matvec_kernel<<<BATCH / 8, 256>>>(x, out);
}

// round 3
// speedup vs baseline: 1.1597x; 1.1597x over previous
#include <cuda_runtime.h>

// out[b] = sum_h sum_k x[b,k]*W[h,k] * (0.5*2.0)
//        = sum_k x[b,k] * S[k],  S[k] = sum_h W[h,k]
// Two HBM-bound passes (~128 MB total). Floor ~ 21us.

#define BATCH 4096
#define IN    4096
#define HID   4096

__device__ __align__(16) float g_S[IN];  // column sums of W (zeroed via memset node)

// Column-sum of W [HID, IN] row-major.
// grid = (IN/1024, HID/ROWS_PER_CTA), block = 256, 4 floats (1 float4) per thread.
__global__ void colsum_kernel(const float* __restrict__ W) {
    const int rows_per_block = 16;
    int k4 = blockIdx.x * blockDim.x + threadIdx.x;   // float4 index along k
    int h0 = blockIdx.y * rows_per_block;

    const float4* Wv = reinterpret_cast<const float4*>(W);
    const int stride4 = IN / 4;

    float4 acc = make_float4(0.f, 0.f, 0.f, 0.f);
    #pragma unroll 16
    for (int r = 0; r < rows_per_block; r++) {
        float4 v = __ldcs(&Wv[(long)(h0 + r) * stride4 + k4]);  // streaming: read-once
        acc.x += v.x; acc.y += v.y; acc.z += v.z; acc.w += v.w;
    }
    // Vector no-return reduction: 1 instruction instead of 4 atomics.
    float* dst = &g_S[k4 * 4];
    asm volatile("red.global.add.v4.f32 [%0], {%1, %2, %3, %4};"
                 :: "l"(dst), "f"(acc.x), "f"(acc.y), "f"(acc.z), "f"(acc.w)
                 : "memory");
}

// Persistent matvec: 1184 CTAs x 256 threads, block-stride over rows.
// out[b] = dot(x[b,:], S)
__global__ void matvec_kernel(const float* __restrict__ x,
                              float* __restrict__ out) {
    const int tid  = threadIdx.x;
    const int lane = tid & 31;
    const int wid  = tid >> 5;

    const float4* Sv = reinterpret_cast<const float4*>(g_S);
    __shared__ float red[8];

    for (int b = blockIdx.x; b < BATCH; b += gridDim.x) {
        const float4* xv = reinterpret_cast<const float4*>(x + (long)b * IN);

        // 1024 float4 per row, 256 threads -> 4 iterations, all coalesced.
        float a0 = 0.f, a1 = 0.f, a2 = 0.f, a3 = 0.f;
        #pragma unroll 4
        for (int i = tid; i < IN / 4; i += 256) {
            float4 xx = __ldcs(&xv[i]);   // streaming: read-once
            float4 ss = Sv[i];            // L2/L1-hot (16 KB)
            a0 = fmaf(xx.x, ss.x, a0);
            a1 = fmaf(xx.y, ss.y, a1);
            a2 = fmaf(xx.z, ss.z, a2);
            a3 = fmaf(xx.w, ss.w, a3);
        }
        float sum = (a0 + a1) + (a2 + a3);

        #pragma unroll
        for (int off = 16; off > 0; off >>= 1)
            sum += __shfl_xor_sync(0xFFFFFFFFu, sum, off);

        if (lane == 0) red[wid] = sum;
        __syncthreads();
        if (wid == 0) {
            float v = (lane < 8) ? red[lane] : 0.f;
            #pragma unroll
            for (int off = 4; off > 0; off >>= 1)
                v += __shfl_xor_sync(0xFFFFFFFFu, v, off);
            if (lane == 0) out[b] = v * (0.5f * 2.0f);
        }
        __syncthreads();
    }
}

extern "C" void kernel_launch(void* const* d_in, const int* in_sizes, int n_in,
                              void* d_out, int out_size) {
    const float* x = (const float*)d_in[0];
    const float* W = (const float*)d_in[1];
    float* out = (float*)d_out;

    void* s_ptr = nullptr;
    cudaGetSymbolAddress(&s_ptr, g_S);
    cudaMemsetAsync(s_ptr, 0, IN * sizeof(float));

    // colsum: 1024 CTAs (4 x 256), 16 rows each -> ~7 CTAs/SM, 55 warps/SM
    dim3 cs_grid(IN / (256 * 4), HID / 16);
    colsum_kernel<<<cs_grid, 256>>>(W);

    // matvec: persistent, exactly 8 CTAs/SM * 148 SMs
    matvec_kernel<<<148 * 8, 256>>>(x, out);
}